// round 12
// baseline (speedup 1.0000x reference)
#include <cuda_runtime.h>
#include <math.h>

#define HW 65536
#define RATIO (127.0f / 255.0f)

// ---------------- scratch (device globals; no allocation) ----------------
__device__ __align__(16) float g_sage[4 * 3 * HW];  // enc planes: mx, av, c1(+b1)
__device__ __align__(16) float g_sagd[8 * 3 * HW];  // dec PARTIAL planes per (half,b): mx, sum, dot
__device__ __align__(16) float g_spat[4 * HW];      // sigmoid spatial gate
__device__ float    g_encsum[4 * 128];
__device__ unsigned g_encmax[4 * 128];
__device__ float    g_decsum[4 * 256];
__device__ unsigned g_decmax[4 * 256];
__device__ float    g_tsm[64];                      // MLP hidden pre-acts
__device__ __align__(16) float g_ch[4 * 128];       // sigmoid channel gate

// monotone float<->uint map for atomicMax/REDUX-max on floats
__device__ __forceinline__ unsigned f2o(float f) {
    unsigned u = __float_as_uint(f);
    return (u & 0x80000000u) ? ~u : (u | 0x80000000u);
}
__device__ __forceinline__ float o2f(unsigned u) {
    return (u & 0x80000000u) ? __uint_as_float(u & 0x7fffffffu) : __uint_as_float(~u);
}

// ================= init (atomic targets) =================
__global__ void k_init() {
    int t = blockIdx.x * blockDim.x + threadIdx.x;
    if (t < 512)  { g_encsum[t] = 0.f; g_encmax[t] = 0u; }
    if (t < 1024) { g_decsum[t] = 0.f; g_decmax[t] = 0x80000000u; }  // f2o(0); relu => v>=0
}

// ================= fused encoder: planes + channel stats =================
// grid (128, 4) x 128 threads: block = 2 rows; thread = (row, float4-col)
__global__ void __launch_bounds__(128) k_enc(const float* __restrict__ xe,
                                             const float* __restrict__ sw1e,
                                             const float* __restrict__ sb1e) {
    __shared__ float    sw[128];
    __shared__ float    psum[4][128];
    __shared__ unsigned pmax[4][128];
    const int t = threadIdx.x;
    if (t < 128) sw[t] = sw1e[t];
    __syncthreads();
    const int y = blockIdx.x * 2 + (t >> 6), c4 = t & 63, b = blockIdx.y;
    const int warp = t >> 5, lane = t & 31;
    const float4* base = (const float4*)(xe + (size_t)b * 128 * HW + y * 256) + c4;

    float4 mx = make_float4(-3.4e38f, -3.4e38f, -3.4e38f, -3.4e38f);
    float4 sm = make_float4(0.f, 0.f, 0.f, 0.f);
    float4 dt = make_float4(0.f, 0.f, 0.f, 0.f);
    float    racc[4] = {0.f, 0.f, 0.f, 0.f};
    unsigned rmx[4]  = {0u, 0u, 0u, 0u};

#pragma unroll
    for (int q = 0; q < 4; q++) {
#pragma unroll 4
        for (int cc = 0; cc < 32; cc++) {
            const int c = q * 32 + cc;
            float4 v = base[(size_t)c * (HW / 4)];
            float wc = sw[c];
            mx.x = fmaxf(mx.x, v.x); sm.x += v.x; dt.x = fmaf(wc, v.x, dt.x);
            mx.y = fmaxf(mx.y, v.y); sm.y += v.y; dt.y = fmaf(wc, v.y, dt.y);
            mx.z = fmaxf(mx.z, v.z); sm.z += v.z; dt.z = fmaf(wc, v.z, dt.z);
            mx.w = fmaxf(mx.w, v.w); sm.w += v.w; dt.w = fmaf(wc, v.w, dt.w);
            float cs = (v.x + v.y) + (v.z + v.w);
            float cm = fmaxf(fmaxf(v.x, v.y), fmaxf(v.z, v.w));
#pragma unroll
            for (int o = 16; o; o >>= 1)
                cs += __shfl_xor_sync(0xffffffffu, cs, o);
            unsigned rm = __reduce_max_sync(0xffffffffu, f2o(cm));
            if (lane == cc) { racc[q] += cs; rmx[q] = max(rmx[q], rm); }
        }
    }
#pragma unroll
    for (int q = 0; q < 4; q++) {
        psum[warp][q * 32 + lane] = racc[q];
        pmax[warp][q * 32 + lane] = rmx[q];
    }
    __syncthreads();
    if (t < 128) {
        float s = (psum[0][t] + psum[1][t]) + (psum[2][t] + psum[3][t]);
        unsigned m = max(max(pmax[0][t], pmax[1][t]), max(pmax[2][t], pmax[3][t]));
        atomicAdd(&g_encsum[b * 128 + t], s);
        atomicMax(&g_encmax[b * 128 + t], m);
    }
    const float b1 = sb1e[0];
    sm.x *= (1.f / 128.f); sm.y *= (1.f / 128.f); sm.z *= (1.f / 128.f); sm.w *= (1.f / 128.f);
    dt.x += b1; dt.y += b1; dt.z += b1; dt.w += b1;
    const size_t p4 = (size_t)(y * 256) / 4 + c4;
    float4* eb = (float4*)(g_sage + (size_t)b * 3 * HW);
    eb[p4]              = mx;
    eb[HW / 4 + p4]     = sm;
    eb[2 * HW / 4 + p4] = dt;
}

// ---------- templated decoder inner loop (compile-time row-select pattern) ----------
// L1,L2,L3 = lo[1..3] (lo[0]==0 always). hl_k = h[Lk], hh_k = h[Lk+1].
template<int L1, int L2, int L3>
__device__ __forceinline__ void dec_loop(
        const float* __restrict__ pcb, const float* sw,
        float (&buf)[2][8 * 512],
        const int t, const int lane,
        const int gA, const int gB,
        const int j0, const int j1, const float wx,
        const float (&wy)[4],
        float (&mx)[4], float (&sm)[4], float (&dt)[4],
        float (&racc)[4], unsigned (&rmx)[4]) {
    constexpr int NH = L3 + 2;   // number of horizontal lerps needed (3 or 4)
#pragma unroll
    for (int s = 0; s < 4; s++) {            // 32-channel slot (compile-time)
        for (int gi = 0; gi < 4; gi++) {     // 8-channel group within slot
            const int g = s * 4 + gi;
            const int cur = g & 1;
            float rr[16];
            const bool pf = (g < 15);
            if (pf) {
                const float* pn = pcb + (size_t)(g + 1) * 8 * 16384;
#pragma unroll
                for (int q = 0; q < 8; q++) {
                    rr[q * 2]     = pn[(size_t)q * 16384 + gA];
                    rr[q * 2 + 1] = pn[(size_t)q * 16384 + gB];
                }
            }
#pragma unroll
            for (int q = 0; q < 8; q++) {
                const int c = g * 8 + q;
                const float* S = &buf[cur][q * 512];
                float h[4];
#pragma unroll
                for (int r = 0; r < NH; r++) {
                    const float a = S[r * 128 + j0];
                    h[r] = fmaf(wx, S[r * 128 + j1] - a, a);
                }
                const float wc = sw[c];
                float v0 = fmaf(wy[0], h[1]      - h[0],  h[0]);
                float v1 = fmaf(wy[1], h[L1 + 1] - h[L1], h[L1]);
                float v2 = fmaf(wy[2], h[L2 + 1] - h[L2], h[L2]);
                float v3 = fmaf(wy[3], h[L3 + 1] - h[L3], h[L3]);
                v0 = fmaxf(v0, 0.f); v1 = fmaxf(v1, 0.f);
                v2 = fmaxf(v2, 0.f); v3 = fmaxf(v3, 0.f);
                mx[0] = fmaxf(mx[0], v0); sm[0] += v0; dt[0] = fmaf(wc, v0, dt[0]);
                mx[1] = fmaxf(mx[1], v1); sm[1] += v1; dt[1] = fmaf(wc, v1, dt[1]);
                mx[2] = fmaxf(mx[2], v2); sm[2] += v2; dt[2] = fmaf(wc, v2, dt[2]);
                mx[3] = fmaxf(mx[3], v3); sm[3] += v3; dt[3] = fmaf(wc, v3, dt[3]);
                float cs = (v0 + v1) + (v2 + v3);
                float cm = fmaxf(fmaxf(v0, v1), fmaxf(v2, v3));
#pragma unroll
                for (int o = 16; o; o >>= 1)
                    cs += __shfl_xor_sync(0xffffffffu, cs, o);
                unsigned rm = __reduce_max_sync(0xffffffffu, f2o(cm));
                if (lane == (c & 31)) { racc[s] += cs; rmx[s] = max(rmx[s], rm); }
            }
            if (pf) {
#pragma unroll
                for (int q = 0; q < 8; q++) {
                    buf[cur ^ 1][q * 512 + t]       = rr[q * 2];
                    buf[cur ^ 1][q * 512 + 256 + t] = rr[q * 2 + 1];
                }
            }
            __syncthreads();
        }
    }
}

// generic fallback (runtime lo, selects) — should never trigger; safety net
__device__ __noinline__ void dec_loop_gen(
        const float* __restrict__ pcb, const float* sw,
        float (&buf)[2][8 * 512],
        const int t, const int lane,
        const int gA, const int gB,
        const int j0, const int j1, const float wx,
        const float (&wy)[4], const int (&lo)[4],
        float (&mx)[4], float (&sm)[4], float (&dt)[4],
        float (&racc)[4], unsigned (&rmx)[4]) {
#pragma unroll
    for (int s = 0; s < 4; s++) {
        for (int gi = 0; gi < 4; gi++) {
            const int g = s * 4 + gi;
            const int cur = g & 1;
            float rr[16];
            const bool pf = (g < 15);
            if (pf) {
                const float* pn = pcb + (size_t)(g + 1) * 8 * 16384;
#pragma unroll
                for (int q = 0; q < 8; q++) {
                    rr[q * 2]     = pn[(size_t)q * 16384 + gA];
                    rr[q * 2 + 1] = pn[(size_t)q * 16384 + gB];
                }
            }
#pragma unroll
            for (int q = 0; q < 8; q++) {
                const int c = g * 8 + q;
                const float* S = &buf[cur][q * 512];
                float h[4];
#pragma unroll
                for (int r = 0; r < 4; r++) {
                    const float a = S[r * 128 + j0];
                    h[r] = fmaf(wx, S[r * 128 + j1] - a, a);
                }
                const float wc = sw[c];
                float cs = 0.f, cm = 0.f;
#pragma unroll
                for (int k = 0; k < 4; k++) {
                    float hl = (lo[k] == 0) ? h[0] : ((lo[k] == 1) ? h[1] : h[2]);
                    float hh = (lo[k] == 0) ? h[1] : ((lo[k] == 1) ? h[2] : h[3]);
                    float v = fmaf(wy[k], hh - hl, hl);
                    v = fmaxf(v, 0.f);
                    mx[k] = fmaxf(mx[k], v); sm[k] += v; dt[k] = fmaf(wc, v, dt[k]);
                    cs += v; cm = fmaxf(cm, v);
                }
#pragma unroll
                for (int o = 16; o; o >>= 1)
                    cs += __shfl_xor_sync(0xffffffffu, cs, o);
                unsigned rm = __reduce_max_sync(0xffffffffu, f2o(cm));
                if (lane == (c & 31)) { racc[s] += cs; rmx[s] = max(rmx[s], rm); }
            }
            if (pf) {
#pragma unroll
                for (int q = 0; q < 8; q++) {
                    buf[cur ^ 1][q * 512 + t]       = rr[q * 2];
                    buf[cur ^ 1][q * 512 + 256 + t] = rr[q * 2 + 1];
                }
            }
            __syncthreads();
        }
    }
}

// ================= fused decoder: partial planes + channel stats =================
// grid (64, 2, 4): x = row-group (4 rows), y = channel half, z = b. 256 threads = columns.
__global__ void __launch_bounds__(256) k_dec_pix(const float* __restrict__ xd,
                                                 const float* __restrict__ sw1d) {
    __shared__ float    sw[128];
    __shared__ float    buf[2][8 * 512];
    __shared__ float    psum[8][128];
    __shared__ unsigned pmaxs[8][128];
    const int t = threadIdx.x, half = blockIdx.y, b = blockIdx.z;
    const int warp = t >> 5, lane = t & 31;
    const int y0 = blockIdx.x * 4;
    if (t < 128) sw[t] = sw1d[half * 128 + t];

    const int rbase = (y0 * 127) / 255;
    int lo[4]; float wy[4];
#pragma unroll
    for (int k = 0; k < 4; k++) {
        const int y = y0 + k;
        const int i0 = (y * 127) / 255;
        lo[k] = i0 - rbase;
        wy[k] = (float)y * RATIO - (float)i0;
    }
    float px = (float)t * RATIO;
    int j0 = min((int)floorf(px), 127), j1 = min(j0 + 1, 127);
    float wx = px - (float)j0;

    const int gA = min(rbase + (t >> 7), 127) * 128 + (t & 127);
    const int gB = min(rbase + 2 + (t >> 7), 127) * 128 + (t & 127);
    const float* pcb = xd + ((size_t)b * 256 + half * 128) * 16384;

#pragma unroll
    for (int q = 0; q < 8; q++) {
        buf[0][q * 512 + t]       = pcb[(size_t)q * 16384 + gA];
        buf[0][q * 512 + 256 + t] = pcb[(size_t)q * 16384 + gB];
    }
    __syncthreads();

    float mx[4] = {0, 0, 0, 0}, sm[4] = {0, 0, 0, 0}, dt[4] = {0, 0, 0, 0};
    float    racc[4] = {0.f, 0.f, 0.f, 0.f};
    unsigned rmx[4]  = {0x80000000u, 0x80000000u, 0x80000000u, 0x80000000u};

    // block-uniform dispatch on the (proven-exhaustive) 4 patterns
    const int code = (lo[1] << 4) | (lo[2] << 2) | lo[3];
    if      (code == 1)  dec_loop<0, 0, 1>(pcb, sw, buf, t, lane, gA, gB, j0, j1, wx, wy, mx, sm, dt, racc, rmx);
    else if (code == 5)  dec_loop<0, 1, 1>(pcb, sw, buf, t, lane, gA, gB, j0, j1, wx, wy, mx, sm, dt, racc, rmx);
    else if (code == 21) dec_loop<1, 1, 1>(pcb, sw, buf, t, lane, gA, gB, j0, j1, wx, wy, mx, sm, dt, racc, rmx);
    else if (code == 22) dec_loop<1, 1, 2>(pcb, sw, buf, t, lane, gA, gB, j0, j1, wx, wy, mx, sm, dt, racc, rmx);
    else                 dec_loop_gen(pcb, sw, buf, t, lane, gA, gB, j0, j1, wx, wy, lo, mx, sm, dt, racc, rmx);

    // bank stats: cross-warp combine, one atomic pair per (block, channel)
#pragma unroll
    for (int s = 0; s < 4; s++) {
        psum[warp][s * 32 + lane]  = racc[s];
        pmaxs[warp][s * 32 + lane] = rmx[s];
    }
    __syncthreads();
    if (t < 128) {
        float    ssum = 0.f;
        unsigned smx  = 0x80000000u;
#pragma unroll
        for (int w = 0; w < 8; w++) {
            ssum += psum[w][t];
            smx = max(smx, pmaxs[w][t]);
        }
        atomicAdd(&g_decsum[b * 256 + half * 128 + t], ssum);
        atomicMax(&g_decmax[b * 256 + half * 128 + t], smx);
    }
    const size_t db = (size_t)(half * 4 + b) * 3 * HW;
#pragma unroll
    for (int k = 0; k < 4; k++) {
        const int p = (y0 + k) * 256 + t;
        g_sagd[db + p]          = mx[k];
        g_sagd[db + HW + p]     = sm[k];
        g_sagd[db + 2 * HW + p] = dt[k];
    }
}

// ================= channel MLP stage 1: hidden pre-activations =================
// grid (16, 4): n = blockIdx.x, b = blockIdx.y; 128 threads
__global__ void __launch_bounds__(128) k_mlp1(
        const float* __restrict__ cwea, const float* __restrict__ cbea,
        const float* __restrict__ cwem, const float* __restrict__ cbem,
        const float* __restrict__ cwda, const float* __restrict__ cbda,
        const float* __restrict__ cwdm, const float* __restrict__ cbdm) {
    __shared__ float red[128];
    const int n = blockIdx.x, b = blockIdx.y, t = threadIdx.x;
    float acc = g_encsum[b * 128 + t] * (1.f / 65536.f) * cwea[n * 128 + t]
              + o2f(g_encmax[b * 128 + t]) * cwem[n * 128 + t];
    acc += g_decsum[b * 256 + t] * (1.f / 65536.f) * cwda[n * 256 + t]
         + o2f(g_decmax[b * 256 + t]) * cwdm[n * 256 + t];
    acc += g_decsum[b * 256 + 128 + t] * (1.f / 65536.f) * cwda[n * 256 + 128 + t]
         + o2f(g_decmax[b * 256 + 128 + t]) * cwdm[n * 256 + 128 + t];
    if (t == 0) acc += cbea[n] + cbem[n] + cbda[n] + cbdm[n];
    red[t] = acc;
    __syncthreads();
    for (int o = 64; o > 0; o >>= 1) {
        if (t < o) red[t] += red[t + o];
        __syncthreads();
    }
    if (t == 0) g_tsm[b * 16 + n] = red[0];
}

// ================= channel MLP stage 2: 16 -> 128 sigmoid =================
__global__ void __launch_bounds__(512) k_mlp2(const float* __restrict__ cwf,
                                              const float* __restrict__ cbf) {
    const int t = threadIdx.x;              // 512: b = t>>7, o = t&127
    const int b = t >> 7, o = t & 127;
    float a = cbf[o];
#pragma unroll
    for (int q = 0; q < 16; q++) a = fmaf(g_tsm[b * 16 + q], cwf[o * 16 + q], a);
    g_ch[t] = 1.f / (1.f + __expf(-a));
}

// ================= fused 7x7 conv (6 planes, combines dec halves) + sigmoid =================
// grid (16, 16, 4): 16x16 output tile, 256 threads, 1 output/thread
__global__ void __launch_bounds__(256) k_conv(const float* __restrict__ sw2e,
                                              const float* __restrict__ sw2d,
                                              const float* __restrict__ sb2e,
                                              const float* __restrict__ sb2d,
                                              const float* __restrict__ sb1d) {
    __shared__ float pl[6][22 * 22];
    __shared__ float wsm[294];
    __shared__ float bv;
    const int tid = threadIdx.x;
    const int X0 = blockIdx.x * 16, Y0 = blockIdx.y * 16, b = blockIdx.z;
    for (int i = tid; i < 294; i += 256)
        wsm[i] = (i < 147) ? sw2e[i] : sw2d[i - 147];
    if (tid == 0) bv = sb2e[0] + sb2d[0];
    const float sb1 = __ldg(sb1d);
    const size_t eb = (size_t)b * 3 * HW;
    const size_t d0 = (size_t)b * 3 * HW;        // half 0
    const size_t d1 = (size_t)(4 + b) * 3 * HW;  // half 1
    for (int idx = tid; idx < 22 * 22; idx += 256) {
        int ry = idx / 22, rx = idx - ry * 22;
        int gy = Y0 + ry - 3, gx = X0 + rx - 3;
        float v0 = 0, v1 = 0, v2 = 0, v3 = 0, v4 = 0, v5 = 0;
        if (gy >= 0 && gy < 256 && gx >= 0 && gx < 256) {
            int p = gy * 256 + gx;
            v0 = g_sage[eb + p];
            v1 = g_sage[eb + HW + p];
            v2 = g_sage[eb + 2 * HW + p];
            v3 = fmaxf(g_sagd[d0 + p], g_sagd[d1 + p]);
            v4 = (g_sagd[d0 + HW + p] + g_sagd[d1 + HW + p]) * (1.f / 256.f);
            v5 = g_sagd[d0 + 2 * HW + p] + g_sagd[d1 + 2 * HW + p] + sb1;
        }
        pl[0][idx] = v0; pl[1][idx] = v1; pl[2][idx] = v2;
        pl[3][idx] = v3; pl[4][idx] = v4; pl[5][idx] = v5;
    }
    __syncthreads();
    const int tx = tid & 15, ty = tid >> 4;
    float acc = bv;
    for (int pp = 0; pp < 6; pp++)
#pragma unroll
        for (int ky = 0; ky < 7; ky++)
#pragma unroll
            for (int kx = 0; kx < 7; kx++)
                acc = fmaf(pl[pp][(ty + ky) * 22 + tx + kx], wsm[pp * 49 + ky * 7 + kx], acc);
    g_spat[(size_t)b * HW + (Y0 + ty) * 256 + X0 + tx] = 1.f / (1.f + __expf(-acc));
}

// ================= final multiply =================
__global__ void __launch_bounds__(256) k_final(const float* __restrict__ xe,
                                               float* __restrict__ out) {
    const int bc = blockIdx.y;
    const int b  = bc >> 7;
    const int i  = blockIdx.x * 256 + threadIdx.x;
    const float s = g_ch[bc];
    float4 xv = reinterpret_cast<const float4*>(xe)[(size_t)bc * 16384 + i];
    float4 sp = reinterpret_cast<const float4*>(g_spat)[(size_t)b * 16384 + i];
    float4 o;
    o.x = xv.x * sp.x * s;
    o.y = xv.y * sp.y * s;
    o.z = xv.z * sp.z * s;
    o.w = xv.w * sp.w * s;
    reinterpret_cast<float4*>(out)[(size_t)bc * 16384 + i] = o;
}

// ================= launch =================
extern "C" void kernel_launch(void* const* d_in, const int* in_sizes, int n_in,
                              void* d_out, int out_size) {
    const float* xe   = (const float*)d_in[0];
    const float* xd   = (const float*)d_in[1];
    const float* cwea = (const float*)d_in[2];
    const float* cbea = (const float*)d_in[3];
    const float* cwem = (const float*)d_in[4];
    const float* cbem = (const float*)d_in[5];
    const float* cwda = (const float*)d_in[6];
    const float* cbda = (const float*)d_in[7];
    const float* cwdm = (const float*)d_in[8];
    const float* cbdm = (const float*)d_in[9];
    const float* cwf  = (const float*)d_in[10];
    const float* cbf  = (const float*)d_in[11];
    const float* sw1e = (const float*)d_in[12];
    const float* sb1e = (const float*)d_in[13];
    const float* sw2e = (const float*)d_in[14];
    const float* sb2e = (const float*)d_in[15];
    const float* sw1d = (const float*)d_in[16];
    const float* sb1d = (const float*)d_in[17];
    const float* sw2d = (const float*)d_in[18];
    const float* sb2d = (const float*)d_in[19];
    float* out = (float*)d_out;

    k_init<<<1, 1024>>>();
    k_enc<<<dim3(128, 4), 128>>>(xe, sw1e, sb1e);
    k_dec_pix<<<dim3(64, 2, 4), 256>>>(xd, sw1d);
    k_mlp1<<<dim3(16, 4), 128>>>(cwea, cbea, cwem, cbem, cwda, cbda, cwdm, cbdm);
    k_mlp2<<<1, 512>>>(cwf, cbf);
    k_conv<<<dim3(16, 16, 4), 256>>>(sw2e, sw2d, sb2e, sb2d, sb1d);
    k_final<<<dim3(64, 512), 256>>>(xe, out);
}

// round 13
// speedup vs baseline: 1.3250x; 1.3250x over previous
#include <cuda_runtime.h>
#include <math.h>

#define HW 65536
#define RATIO (127.0f / 255.0f)

// ---------------- scratch (device globals; no allocation) ----------------
__device__ __align__(16) float g_sage[4 * 3 * HW];  // enc planes: mx, av, c1(+b1)
__device__ __align__(16) float g_sagd[8 * 3 * HW];  // dec PARTIAL planes per (half,b): mx, sum, dot
__device__ __align__(16) float g_spat[4 * HW];      // sigmoid spatial gate
__device__ float    g_encsum[4 * 128];
__device__ unsigned g_encmax[4 * 128];
__device__ float    g_decsum[4 * 256];
__device__ unsigned g_decmax[4 * 256];
__device__ float    g_tsm[64];                      // MLP hidden pre-acts
__device__ __align__(16) float g_ch[4 * 128];       // sigmoid channel gate

// monotone float<->uint map for atomicMax/REDUX-max on floats
__device__ __forceinline__ unsigned f2o(float f) {
    unsigned u = __float_as_uint(f);
    return (u & 0x80000000u) ? ~u : (u | 0x80000000u);
}
__device__ __forceinline__ float o2f(unsigned u) {
    return (u & 0x80000000u) ? __uint_as_float(u & 0x7fffffffu) : __uint_as_float(~u);
}

// ================= init (atomic targets) =================
__global__ void k_init() {
    int t = blockIdx.x * blockDim.x + threadIdx.x;
    if (t < 512)  { g_encsum[t] = 0.f; g_encmax[t] = 0u; }
    if (t < 1024) { g_decsum[t] = 0.f; g_decmax[t] = 0x80000000u; }  // f2o(0); relu => v>=0
}

// ================= fused encoder: planes + channel stats =================
// grid (128, 4) x 128 threads: block = 2 rows; thread = (row, float4-col)
__global__ void __launch_bounds__(128) k_enc(const float* __restrict__ xe,
                                             const float* __restrict__ sw1e,
                                             const float* __restrict__ sb1e) {
    __shared__ float    sw[128];
    __shared__ float    psum[4][128];
    __shared__ unsigned pmax[4][128];
    const int t = threadIdx.x;
    if (t < 128) sw[t] = sw1e[t];
    __syncthreads();
    const int y = blockIdx.x * 2 + (t >> 6), c4 = t & 63, b = blockIdx.y;
    const int warp = t >> 5, lane = t & 31;
    const float4* base = (const float4*)(xe + (size_t)b * 128 * HW + y * 256) + c4;

    float4 mx = make_float4(-3.4e38f, -3.4e38f, -3.4e38f, -3.4e38f);
    float4 sm = make_float4(0.f, 0.f, 0.f, 0.f);
    float4 dt = make_float4(0.f, 0.f, 0.f, 0.f);
    float    racc[4] = {0.f, 0.f, 0.f, 0.f};
    unsigned rmx[4]  = {0u, 0u, 0u, 0u};

#pragma unroll
    for (int q = 0; q < 4; q++) {
#pragma unroll 4
        for (int cc = 0; cc < 32; cc++) {
            const int c = q * 32 + cc;
            float4 v = base[(size_t)c * (HW / 4)];
            float wc = sw[c];
            mx.x = fmaxf(mx.x, v.x); sm.x += v.x; dt.x = fmaf(wc, v.x, dt.x);
            mx.y = fmaxf(mx.y, v.y); sm.y += v.y; dt.y = fmaf(wc, v.y, dt.y);
            mx.z = fmaxf(mx.z, v.z); sm.z += v.z; dt.z = fmaf(wc, v.z, dt.z);
            mx.w = fmaxf(mx.w, v.w); sm.w += v.w; dt.w = fmaf(wc, v.w, dt.w);
            float cs = (v.x + v.y) + (v.z + v.w);
            float cm = fmaxf(fmaxf(v.x, v.y), fmaxf(v.z, v.w));
#pragma unroll
            for (int o = 16; o; o >>= 1)
                cs += __shfl_xor_sync(0xffffffffu, cs, o);
            unsigned rm = __reduce_max_sync(0xffffffffu, f2o(cm));
            if (lane == cc) { racc[q] += cs; rmx[q] = max(rmx[q], rm); }
        }
    }
#pragma unroll
    for (int q = 0; q < 4; q++) {
        psum[warp][q * 32 + lane] = racc[q];
        pmax[warp][q * 32 + lane] = rmx[q];
    }
    __syncthreads();
    if (t < 128) {
        float s = (psum[0][t] + psum[1][t]) + (psum[2][t] + psum[3][t]);
        unsigned m = max(max(pmax[0][t], pmax[1][t]), max(pmax[2][t], pmax[3][t]));
        atomicAdd(&g_encsum[b * 128 + t], s);
        atomicMax(&g_encmax[b * 128 + t], m);
    }
    const float b1 = sb1e[0];
    sm.x *= (1.f / 128.f); sm.y *= (1.f / 128.f); sm.z *= (1.f / 128.f); sm.w *= (1.f / 128.f);
    dt.x += b1; dt.y += b1; dt.z += b1; dt.w += b1;
    const size_t p4 = (size_t)(y * 256) / 4 + c4;
    float4* eb = (float4*)(g_sage + (size_t)b * 3 * HW);
    eb[p4]              = mx;
    eb[HW / 4 + p4]     = sm;
    eb[2 * HW / 4 + p4] = dt;
}

// ================= fused decoder: partial planes + channel stats (R11 single body) =================
// grid (64, 2, 4): x = row-group (4 rows), y = channel half, z = b. 256 threads = columns.
__global__ void __launch_bounds__(256) k_dec_pix(const float* __restrict__ xd,
                                                 const float* __restrict__ sw1d) {
    __shared__ float    sw[128];
    __shared__ float    buf[2][8 * 512];   // [buf][q*512 + srcrow*128 + col]
    __shared__ float    psum[8][128];
    __shared__ unsigned pmaxs[8][128];
    const int t = threadIdx.x, half = blockIdx.y, b = blockIdx.z;
    const int warp = t >> 5, lane = t & 31;
    const int y0 = blockIdx.x * 4;
    if (t < 128) sw[t] = sw1d[half * 128 + t];

    const int rbase = (y0 * 127) / 255;
    int lo[4]; float wy[4];
#pragma unroll
    for (int k = 0; k < 4; k++) {
        const int y = y0 + k;
        const int i0 = (y * 127) / 255;          // exact floor
        lo[k] = i0 - rbase;                      // 0..2, uniform per block
        wy[k] = (float)y * RATIO - (float)i0;
    }
    float px = (float)t * RATIO;
    int j0 = min((int)floorf(px), 127), j1 = min(j0 + 1, 127);
    float wx = px - (float)j0;

    const int gA = min(rbase + (t >> 7), 127) * 128 + (t & 127);
    const int gB = min(rbase + 2 + (t >> 7), 127) * 128 + (t & 127);
    const float* pcb = xd + ((size_t)b * 256 + half * 128) * 16384;

#pragma unroll
    for (int q = 0; q < 8; q++) {
        buf[0][q * 512 + t]       = pcb[(size_t)q * 16384 + gA];
        buf[0][q * 512 + 256 + t] = pcb[(size_t)q * 16384 + gB];
    }
    __syncthreads();

    float mx[4] = {0, 0, 0, 0}, sm[4] = {0, 0, 0, 0}, dt[4] = {0, 0, 0, 0};
    float    racc[4] = {0.f, 0.f, 0.f, 0.f};
    unsigned rmx[4]  = {0x80000000u, 0x80000000u, 0x80000000u, 0x80000000u};

#pragma unroll
    for (int s = 0; s < 4; s++) {            // 32-channel slot (compile-time)
        for (int gi = 0; gi < 4; gi++) {     // 8-channel group within slot
            const int g = s * 4 + gi;
            const int cur = g & 1;
            float rr[16];
            const bool pf = (g < 15);
            if (pf) {
                const float* pn = pcb + (size_t)(g + 1) * 8 * 16384;
#pragma unroll
                for (int q = 0; q < 8; q++) {
                    rr[q * 2]     = pn[(size_t)q * 16384 + gA];
                    rr[q * 2 + 1] = pn[(size_t)q * 16384 + gB];
                }
            }
#pragma unroll
            for (int q = 0; q < 8; q++) {
                const int c = g * 8 + q;
                const float* S = &buf[cur][q * 512];
                float h0, h1, h2, h3;
                { float a = S[j0],       bb = S[j1];       h0 = fmaf(wx, bb - a, a); }
                { float a = S[128 + j0], bb = S[128 + j1]; h1 = fmaf(wx, bb - a, a); }
                { float a = S[256 + j0], bb = S[256 + j1]; h2 = fmaf(wx, bb - a, a); }
                { float a = S[384 + j0], bb = S[384 + j1]; h3 = fmaf(wx, bb - a, a); }
                const float wc = sw[c];
                float cs = 0.f, cm = 0.f;
#pragma unroll
                for (int k = 0; k < 4; k++) {
                    float hl = (lo[k] == 0) ? h0 : ((lo[k] == 1) ? h1 : h2);
                    float hh = (lo[k] == 0) ? h1 : ((lo[k] == 1) ? h2 : h3);
                    float v = fmaf(wy[k], hh - hl, hl);
                    v = fmaxf(v, 0.f);
                    mx[k] = fmaxf(mx[k], v);
                    sm[k] += v;
                    dt[k] = fmaf(wc, v, dt[k]);
                    cs += v;
                    cm = fmaxf(cm, v);
                }
#pragma unroll
                for (int o = 16; o; o >>= 1)
                    cs += __shfl_xor_sync(0xffffffffu, cs, o);
                unsigned rm = __reduce_max_sync(0xffffffffu, f2o(cm));
                if (lane == (c & 31)) { racc[s] += cs; rmx[s] = max(rmx[s], rm); }
            }
            if (pf) {
#pragma unroll
                for (int q = 0; q < 8; q++) {
                    buf[cur ^ 1][q * 512 + t]       = rr[q * 2];
                    buf[cur ^ 1][q * 512 + 256 + t] = rr[q * 2 + 1];
                }
            }
            __syncthreads();
        }
    }
    // bank stats: cross-warp combine, one atomic pair per (block, channel)
#pragma unroll
    for (int s = 0; s < 4; s++) {
        psum[warp][s * 32 + lane]  = racc[s];
        pmaxs[warp][s * 32 + lane] = rmx[s];
    }
    __syncthreads();
    if (t < 128) {
        float    ssum = 0.f;
        unsigned smx  = 0x80000000u;
#pragma unroll
        for (int w = 0; w < 8; w++) {
            ssum += psum[w][t];
            smx = max(smx, pmaxs[w][t]);
        }
        atomicAdd(&g_decsum[b * 256 + half * 128 + t], ssum);
        atomicMax(&g_decmax[b * 256 + half * 128 + t], smx);
    }
    const size_t db = (size_t)(half * 4 + b) * 3 * HW;
#pragma unroll
    for (int k = 0; k < 4; k++) {
        const int p = (y0 + k) * 256 + t;
        g_sagd[db + p]          = mx[k];
        g_sagd[db + HW + p]     = sm[k];
        g_sagd[db + 2 * HW + p] = dt[k];
    }
}

// ================= channel MLP stage 1: hidden pre-activations =================
// grid (16, 4): n = blockIdx.x, b = blockIdx.y; 128 threads
__global__ void __launch_bounds__(128) k_mlp1(
        const float* __restrict__ cwea, const float* __restrict__ cbea,
        const float* __restrict__ cwem, const float* __restrict__ cbem,
        const float* __restrict__ cwda, const float* __restrict__ cbda,
        const float* __restrict__ cwdm, const float* __restrict__ cbdm) {
    __shared__ float red[128];
    const int n = blockIdx.x, b = blockIdx.y, t = threadIdx.x;
    float acc = g_encsum[b * 128 + t] * (1.f / 65536.f) * cwea[n * 128 + t]
              + o2f(g_encmax[b * 128 + t]) * cwem[n * 128 + t];
    acc += g_decsum[b * 256 + t] * (1.f / 65536.f) * cwda[n * 256 + t]
         + o2f(g_decmax[b * 256 + t]) * cwdm[n * 256 + t];
    acc += g_decsum[b * 256 + 128 + t] * (1.f / 65536.f) * cwda[n * 256 + 128 + t]
         + o2f(g_decmax[b * 256 + 128 + t]) * cwdm[n * 256 + 128 + t];
    if (t == 0) acc += cbea[n] + cbem[n] + cbda[n] + cbdm[n];
    red[t] = acc;
    __syncthreads();
    for (int o = 64; o > 0; o >>= 1) {
        if (t < o) red[t] += red[t + o];
        __syncthreads();
    }
    if (t == 0) g_tsm[b * 16 + n] = red[0];
}

// ================= channel MLP stage 2: 16 -> 128 sigmoid =================
__global__ void __launch_bounds__(512) k_mlp2(const float* __restrict__ cwf,
                                              const float* __restrict__ cbf) {
    const int t = threadIdx.x;              // 512: b = t>>7, o = t&127
    const int b = t >> 7, o = t & 127;
    float a = cbf[o];
#pragma unroll
    for (int q = 0; q < 16; q++) a = fmaf(g_tsm[b * 16 + q], cwf[o * 16 + q], a);
    g_ch[t] = 1.f / (1.f + __expf(-a));
}

// ================= fused 7x7 conv (6 planes, combines dec halves) + sigmoid =================
// grid (16, 16, 4): 16x16 output tile, 256 threads, 1 output/thread
__global__ void __launch_bounds__(256) k_conv(const float* __restrict__ sw2e,
                                              const float* __restrict__ sw2d,
                                              const float* __restrict__ sb2e,
                                              const float* __restrict__ sb2d,
                                              const float* __restrict__ sb1d) {
    __shared__ float pl[6][22 * 22];
    __shared__ float wsm[294];
    __shared__ float bv;
    const int tid = threadIdx.x;
    const int X0 = blockIdx.x * 16, Y0 = blockIdx.y * 16, b = blockIdx.z;
    for (int i = tid; i < 294; i += 256)
        wsm[i] = (i < 147) ? sw2e[i] : sw2d[i - 147];
    if (tid == 0) bv = sb2e[0] + sb2d[0];
    const float sb1 = __ldg(sb1d);
    const size_t eb = (size_t)b * 3 * HW;
    const size_t d0 = (size_t)b * 3 * HW;        // half 0
    const size_t d1 = (size_t)(4 + b) * 3 * HW;  // half 1
    for (int idx = tid; idx < 22 * 22; idx += 256) {
        int ry = idx / 22, rx = idx - ry * 22;
        int gy = Y0 + ry - 3, gx = X0 + rx - 3;
        float v0 = 0, v1 = 0, v2 = 0, v3 = 0, v4 = 0, v5 = 0;
        if (gy >= 0 && gy < 256 && gx >= 0 && gx < 256) {
            int p = gy * 256 + gx;
            v0 = g_sage[eb + p];
            v1 = g_sage[eb + HW + p];
            v2 = g_sage[eb + 2 * HW + p];
            v3 = fmaxf(g_sagd[d0 + p], g_sagd[d1 + p]);
            v4 = (g_sagd[d0 + HW + p] + g_sagd[d1 + HW + p]) * (1.f / 256.f);
            v5 = g_sagd[d0 + 2 * HW + p] + g_sagd[d1 + 2 * HW + p] + sb1;
        }
        pl[0][idx] = v0; pl[1][idx] = v1; pl[2][idx] = v2;
        pl[3][idx] = v3; pl[4][idx] = v4; pl[5][idx] = v5;
    }
    __syncthreads();
    const int tx = tid & 15, ty = tid >> 4;
    float acc = bv;
    for (int pp = 0; pp < 6; pp++)
#pragma unroll
        for (int ky = 0; ky < 7; ky++)
#pragma unroll
            for (int kx = 0; kx < 7; kx++)
                acc = fmaf(pl[pp][(ty + ky) * 22 + tx + kx], wsm[pp * 49 + ky * 7 + kx], acc);
    g_spat[(size_t)b * HW + (Y0 + ty) * 256 + X0 + tx] = 1.f / (1.f + __expf(-acc));
}

// ================= final multiply =================
__global__ void __launch_bounds__(256) k_final(const float* __restrict__ xe,
                                               float* __restrict__ out) {
    const int bc = blockIdx.y;
    const int b  = bc >> 7;
    const int i  = blockIdx.x * 256 + threadIdx.x;
    const float s = g_ch[bc];
    float4 xv = reinterpret_cast<const float4*>(xe)[(size_t)bc * 16384 + i];
    float4 sp = reinterpret_cast<const float4*>(g_spat)[(size_t)b * 16384 + i];
    float4 o;
    o.x = xv.x * sp.x * s;
    o.y = xv.y * sp.y * s;
    o.z = xv.z * sp.z * s;
    o.w = xv.w * sp.w * s;
    reinterpret_cast<float4*>(out)[(size_t)bc * 16384 + i] = o;
}

// ================= launch =================
extern "C" void kernel_launch(void* const* d_in, const int* in_sizes, int n_in,
                              void* d_out, int out_size) {
    const float* xe   = (const float*)d_in[0];
    const float* xd   = (const float*)d_in[1];
    const float* cwea = (const float*)d_in[2];
    const float* cbea = (const float*)d_in[3];
    const float* cwem = (const float*)d_in[4];
    const float* cbem = (const float*)d_in[5];
    const float* cwda = (const float*)d_in[6];
    const float* cbda = (const float*)d_in[7];
    const float* cwdm = (const float*)d_in[8];
    const float* cbdm = (const float*)d_in[9];
    const float* cwf  = (const float*)d_in[10];
    const float* cbf  = (const float*)d_in[11];
    const float* sw1e = (const float*)d_in[12];
    const float* sb1e = (const float*)d_in[13];
    const float* sw2e = (const float*)d_in[14];
    const float* sb2e = (const float*)d_in[15];
    const float* sw1d = (const float*)d_in[16];
    const float* sb1d = (const float*)d_in[17];
    const float* sw2d = (const float*)d_in[18];
    const float* sb2d = (const float*)d_in[19];
    float* out = (float*)d_out;

    k_init<<<1, 1024>>>();
    k_enc<<<dim3(128, 4), 128>>>(xe, sw1e, sb1e);
    k_dec_pix<<<dim3(64, 2, 4), 256>>>(xd, sw1d);
    k_mlp1<<<dim3(16, 4), 128>>>(cwea, cbea, cwem, cbem, cwda, cbda, cwdm, cbdm);
    k_mlp2<<<1, 512>>>(cwf, cbf);
    k_conv<<<dim3(16, 16, 4), 256>>>(sw2e, sw2d, sb2e, sb2d, sb1d);
    k_final<<<dim3(64, 512), 256>>>(xe, out);
}

// round 14
// speedup vs baseline: 1.5771x; 1.1903x over previous
#include <cuda_runtime.h>
#include <math.h>

#define HW 65536
#define RATIO (127.0f / 255.0f)

// ---------------- scratch (device globals; no allocation) ----------------
__device__ __align__(16) float g_sage[4 * 3 * HW];  // enc planes: mx, av, c1(+b1)
__device__ __align__(16) float g_sagd[8 * 3 * HW];  // dec PARTIAL planes per (half,b): mx, sum, dot
__device__ __align__(16) float g_spat[4 * HW];      // sigmoid spatial gate
__device__ float    g_encsum[4 * 128];
__device__ unsigned g_encmax[4 * 128];
__device__ float    g_decsum[4 * 256];
__device__ unsigned g_decmax[4 * 256];
__device__ float    g_tsm[64];                      // MLP hidden pre-acts
__device__ __align__(16) float g_ch[4 * 128];       // sigmoid channel gate

// monotone float<->uint map for atomicMax/REDUX-max on floats
__device__ __forceinline__ unsigned f2o(float f) {
    unsigned u = __float_as_uint(f);
    return (u & 0x80000000u) ? ~u : (u | 0x80000000u);
}
__device__ __forceinline__ float o2f(unsigned u) {
    return (u & 0x80000000u) ? __uint_as_float(u & 0x7fffffffu) : __uint_as_float(~u);
}

// ================= init (atomic targets) =================
__global__ void k_init() {
    int t = blockIdx.x * blockDim.x + threadIdx.x;
    if (t < 512)  { g_encsum[t] = 0.f; g_encmax[t] = 0u; }
    if (t < 1024) { g_decsum[t] = 0.f; g_decmax[t] = 0x80000000u; }  // f2o(0); relu => v>=0
}

// ================= fused encoder: planes + channel stats =================
// grid (128, 4) x 128 threads: block = 2 rows; thread = (row, float4-col)
__global__ void __launch_bounds__(128) k_enc(const float* __restrict__ xe,
                                             const float* __restrict__ sw1e,
                                             const float* __restrict__ sb1e) {
    __shared__ float    sw[128];
    __shared__ float    psum[4][128];
    __shared__ unsigned pmax[4][128];
    const int t = threadIdx.x;
    if (t < 128) sw[t] = sw1e[t];
    __syncthreads();
    const int y = blockIdx.x * 2 + (t >> 6), c4 = t & 63, b = blockIdx.y;
    const int warp = t >> 5, lane = t & 31;
    const float4* base = (const float4*)(xe + (size_t)b * 128 * HW + y * 256) + c4;

    float4 mx = make_float4(-3.4e38f, -3.4e38f, -3.4e38f, -3.4e38f);
    float4 sm = make_float4(0.f, 0.f, 0.f, 0.f);
    float4 dt = make_float4(0.f, 0.f, 0.f, 0.f);
    float    racc[4] = {0.f, 0.f, 0.f, 0.f};
    unsigned rmx[4]  = {0u, 0u, 0u, 0u};

#pragma unroll
    for (int q = 0; q < 4; q++) {
#pragma unroll 4
        for (int cc = 0; cc < 32; cc++) {
            const int c = q * 32 + cc;
            float4 v = base[(size_t)c * (HW / 4)];
            float wc = sw[c];
            mx.x = fmaxf(mx.x, v.x); sm.x += v.x; dt.x = fmaf(wc, v.x, dt.x);
            mx.y = fmaxf(mx.y, v.y); sm.y += v.y; dt.y = fmaf(wc, v.y, dt.y);
            mx.z = fmaxf(mx.z, v.z); sm.z += v.z; dt.z = fmaf(wc, v.z, dt.z);
            mx.w = fmaxf(mx.w, v.w); sm.w += v.w; dt.w = fmaf(wc, v.w, dt.w);
            float cs = (v.x + v.y) + (v.z + v.w);
            float cm = fmaxf(fmaxf(v.x, v.y), fmaxf(v.z, v.w));
#pragma unroll
            for (int o = 16; o; o >>= 1)
                cs += __shfl_xor_sync(0xffffffffu, cs, o);
            unsigned rm = __reduce_max_sync(0xffffffffu, f2o(cm));
            if (lane == cc) { racc[q] += cs; rmx[q] = max(rmx[q], rm); }
        }
    }
#pragma unroll
    for (int q = 0; q < 4; q++) {
        psum[warp][q * 32 + lane] = racc[q];
        pmax[warp][q * 32 + lane] = rmx[q];
    }
    __syncthreads();
    if (t < 128) {
        float s = (psum[0][t] + psum[1][t]) + (psum[2][t] + psum[3][t]);
        unsigned m = max(max(pmax[0][t], pmax[1][t]), max(pmax[2][t], pmax[3][t]));
        atomicAdd(&g_encsum[b * 128 + t], s);
        atomicMax(&g_encmax[b * 128 + t], m);
    }
    const float b1 = sb1e[0];
    sm.x *= (1.f / 128.f); sm.y *= (1.f / 128.f); sm.z *= (1.f / 128.f); sm.w *= (1.f / 128.f);
    dt.x += b1; dt.y += b1; dt.z += b1; dt.w += b1;
    const size_t p4 = (size_t)(y * 256) / 4 + c4;
    float4* eb = (float4*)(g_sage + (size_t)b * 3 * HW);
    eb[p4]              = mx;
    eb[HW / 4 + p4]     = sm;
    eb[2 * HW / 4 + p4] = dt;
}

// ================= fused decoder: partial planes + channel stats =================
// grid (64, 2, 4): x = row-group (4 rows), y = channel half, z = b. 256 threads = columns.
__global__ void __launch_bounds__(256) k_dec_pix(const float* __restrict__ xd,
                                                 const float* __restrict__ sw1d) {
    __shared__ float    sw[128];
    __shared__ float    buf[2][8 * 512];   // [buf][q*512 + srcrow*128 + col]
    __shared__ float    psum[8][128];
    __shared__ unsigned pmaxs[8][128];
    const int t = threadIdx.x, half = blockIdx.y, b = blockIdx.z;
    const int warp = t >> 5, lane = t & 31;
    const int y0 = blockIdx.x * 4;
    if (t < 128) sw[t] = sw1d[half * 128 + t];

    const int rbase = (y0 * 127) / 255;
    int lo[4]; float wy[4];
#pragma unroll
    for (int k = 0; k < 4; k++) {
        const int y = y0 + k;
        const int i0 = (y * 127) / 255;          // exact floor
        lo[k] = i0 - rbase;                      // 0..2, uniform per block
        wy[k] = (float)y * RATIO - (float)i0;
    }
    float px = (float)t * RATIO;
    int j0 = min((int)floorf(px), 127), j1 = min(j0 + 1, 127);
    float wx = px - (float)j0;

    const int gA = min(rbase + (t >> 7), 127) * 128 + (t & 127);
    const int gB = min(rbase + 2 + (t >> 7), 127) * 128 + (t & 127);
    const float* pcb = xd + ((size_t)b * 256 + half * 128) * 16384;

#pragma unroll
    for (int q = 0; q < 8; q++) {
        buf[0][q * 512 + t]       = pcb[(size_t)q * 16384 + gA];
        buf[0][q * 512 + 256 + t] = pcb[(size_t)q * 16384 + gB];
    }
    __syncthreads();

    float mx[4] = {0, 0, 0, 0}, sm[4] = {0, 0, 0, 0}, dt[4] = {0, 0, 0, 0};
    float    racc[4] = {0.f, 0.f, 0.f, 0.f};
    unsigned rmx[4]  = {0x80000000u, 0x80000000u, 0x80000000u, 0x80000000u};

#pragma unroll
    for (int s = 0; s < 4; s++) {            // 32-channel slot (compile-time)
        for (int gi = 0; gi < 4; gi++) {     // 8-channel group within slot
            const int g = s * 4 + gi;
            const int cur = g & 1;
            float rr[16];
            const bool pf = (g < 15);
            if (pf) {
                const float* pn = pcb + (size_t)(g + 1) * 8 * 16384;
#pragma unroll
                for (int q = 0; q < 8; q++) {
                    rr[q * 2]     = pn[(size_t)q * 16384 + gA];
                    rr[q * 2 + 1] = pn[(size_t)q * 16384 + gB];
                }
            }
#pragma unroll
            for (int q = 0; q < 8; q++) {
                const int c = g * 8 + q;
                const float* S = &buf[cur][q * 512];
                float h0, h1, h2, h3;
                { float a = S[j0],       bb = S[j1];       h0 = fmaf(wx, bb - a, a); }
                { float a = S[128 + j0], bb = S[128 + j1]; h1 = fmaf(wx, bb - a, a); }
                { float a = S[256 + j0], bb = S[256 + j1]; h2 = fmaf(wx, bb - a, a); }
                { float a = S[384 + j0], bb = S[384 + j1]; h3 = fmaf(wx, bb - a, a); }
                const float wc = sw[c];
                float cs = 0.f, cm = 0.f;
#pragma unroll
                for (int k = 0; k < 4; k++) {
                    float hl = (lo[k] == 0) ? h0 : ((lo[k] == 1) ? h1 : h2);
                    float hh = (lo[k] == 0) ? h1 : ((lo[k] == 1) ? h2 : h3);
                    float v = fmaf(wy[k], hh - hl, hl);
                    v = fmaxf(v, 0.f);
                    mx[k] = fmaxf(mx[k], v);
                    sm[k] += v;
                    dt[k] = fmaf(wc, v, dt[k]);
                    cs += v;
                    cm = fmaxf(cm, v);
                }
#pragma unroll
                for (int o = 16; o; o >>= 1)
                    cs += __shfl_xor_sync(0xffffffffu, cs, o);
                unsigned rm = __reduce_max_sync(0xffffffffu, f2o(cm));
                if (lane == (c & 31)) { racc[s] += cs; rmx[s] = max(rmx[s], rm); }
            }
            if (pf) {
#pragma unroll
                for (int q = 0; q < 8; q++) {
                    buf[cur ^ 1][q * 512 + t]       = rr[q * 2];
                    buf[cur ^ 1][q * 512 + 256 + t] = rr[q * 2 + 1];
                }
            }
            __syncthreads();
        }
    }
    // bank stats: cross-warp combine, one atomic pair per (block, channel)
#pragma unroll
    for (int s = 0; s < 4; s++) {
        psum[warp][s * 32 + lane]  = racc[s];
        pmaxs[warp][s * 32 + lane] = rmx[s];
    }
    __syncthreads();
    if (t < 128) {
        float    ssum = 0.f;
        unsigned smx  = 0x80000000u;
#pragma unroll
        for (int w = 0; w < 8; w++) {
            ssum += psum[w][t];
            smx = max(smx, pmaxs[w][t]);
        }
        atomicAdd(&g_decsum[b * 256 + half * 128 + t], ssum);
        atomicMax(&g_decmax[b * 256 + half * 128 + t], smx);
    }
    const size_t db = (size_t)(half * 4 + b) * 3 * HW;
#pragma unroll
    for (int k = 0; k < 4; k++) {
        const int p = (y0 + k) * 256 + t;
        g_sagd[db + p]          = mx[k];
        g_sagd[db + HW + p]     = sm[k];
        g_sagd[db + 2 * HW + p] = dt[k];
    }
}

// ================= channel MLP stage 1: hidden pre-activations =================
// grid (16, 4): n = blockIdx.x, b = blockIdx.y; 128 threads
__global__ void __launch_bounds__(128) k_mlp1(
        const float* __restrict__ cwea, const float* __restrict__ cbea,
        const float* __restrict__ cwem, const float* __restrict__ cbem,
        const float* __restrict__ cwda, const float* __restrict__ cbda,
        const float* __restrict__ cwdm, const float* __restrict__ cbdm) {
    __shared__ float red[128];
    const int n = blockIdx.x, b = blockIdx.y, t = threadIdx.x;
    float acc = g_encsum[b * 128 + t] * (1.f / 65536.f) * cwea[n * 128 + t]
              + o2f(g_encmax[b * 128 + t]) * cwem[n * 128 + t];
    acc += g_decsum[b * 256 + t] * (1.f / 65536.f) * cwda[n * 256 + t]
         + o2f(g_decmax[b * 256 + t]) * cwdm[n * 256 + t];
    acc += g_decsum[b * 256 + 128 + t] * (1.f / 65536.f) * cwda[n * 256 + 128 + t]
         + o2f(g_decmax[b * 256 + 128 + t]) * cwdm[n * 256 + 128 + t];
    if (t == 0) acc += cbea[n] + cbem[n] + cbda[n] + cbdm[n];
    red[t] = acc;
    __syncthreads();
    for (int o = 64; o > 0; o >>= 1) {
        if (t < o) red[t] += red[t + o];
        __syncthreads();
    }
    if (t == 0) g_tsm[b * 16 + n] = red[0];
}

// ================= channel MLP stage 2: 16 -> 128 sigmoid =================
__global__ void __launch_bounds__(512) k_mlp2(const float* __restrict__ cwf,
                                              const float* __restrict__ cbf) {
    const int t = threadIdx.x;              // 512: b = t>>7, o = t&127
    const int b = t >> 7, o = t & 127;
    float a = cbf[o];
#pragma unroll
    for (int q = 0; q < 16; q++) a = fmaf(g_tsm[b * 16 + q], cwf[o * 16 + q], a);
    g_ch[t] = 1.f / (1.f + __expf(-a));
}

// ================= fused 7x7 conv (6 planes, combines dec halves) + sigmoid =================
// grid (16, 16, 4): 16x16 output tile, 256 threads, 1 output/thread
__global__ void __launch_bounds__(256) k_conv(const float* __restrict__ sw2e,
                                              const float* __restrict__ sw2d,
                                              const float* __restrict__ sb2e,
                                              const float* __restrict__ sb2d,
                                              const float* __restrict__ sb1d) {
    __shared__ float pl[6][22 * 22];
    __shared__ float wsm[294];
    __shared__ float bv;
    const int tid = threadIdx.x;
    const int X0 = blockIdx.x * 16, Y0 = blockIdx.y * 16, b = blockIdx.z;
    for (int i = tid; i < 294; i += 256)
        wsm[i] = (i < 147) ? sw2e[i] : sw2d[i - 147];
    if (tid == 0) bv = sb2e[0] + sb2d[0];
    const float sb1 = __ldg(sb1d);
    const size_t eb = (size_t)b * 3 * HW;
    const size_t d0 = (size_t)b * 3 * HW;        // half 0
    const size_t d1 = (size_t)(4 + b) * 3 * HW;  // half 1
    for (int idx = tid; idx < 22 * 22; idx += 256) {
        int ry = idx / 22, rx = idx - ry * 22;
        int gy = Y0 + ry - 3, gx = X0 + rx - 3;
        float v0 = 0, v1 = 0, v2 = 0, v3 = 0, v4 = 0, v5 = 0;
        if (gy >= 0 && gy < 256 && gx >= 0 && gx < 256) {
            int p = gy * 256 + gx;
            v0 = g_sage[eb + p];
            v1 = g_sage[eb + HW + p];
            v2 = g_sage[eb + 2 * HW + p];
            v3 = fmaxf(g_sagd[d0 + p], g_sagd[d1 + p]);
            v4 = (g_sagd[d0 + HW + p] + g_sagd[d1 + HW + p]) * (1.f / 256.f);
            v5 = g_sagd[d0 + 2 * HW + p] + g_sagd[d1 + 2 * HW + p] + sb1;
        }
        pl[0][idx] = v0; pl[1][idx] = v1; pl[2][idx] = v2;
        pl[3][idx] = v3; pl[4][idx] = v4; pl[5][idx] = v5;
    }
    __syncthreads();
    const int tx = tid & 15, ty = tid >> 4;
    float acc = bv;
    for (int pp = 0; pp < 6; pp++)
#pragma unroll
        for (int ky = 0; ky < 7; ky++)
#pragma unroll
            for (int kx = 0; kx < 7; kx++)
                acc = fmaf(pl[pp][(ty + ky) * 22 + tx + kx], wsm[pp * 49 + ky * 7 + kx], acc);
    g_spat[(size_t)b * HW + (Y0 + ty) * 256 + X0 + tx] = 1.f / (1.f + __expf(-acc));
}

// ================= final multiply =================
__global__ void __launch_bounds__(256) k_final(const float* __restrict__ xe,
                                               float* __restrict__ out) {
    const int bc = blockIdx.y;
    const int b  = bc >> 7;
    const int i  = blockIdx.x * 256 + threadIdx.x;
    const float s = g_ch[bc];
    float4 xv = reinterpret_cast<const float4*>(xe)[(size_t)bc * 16384 + i];
    float4 sp = reinterpret_cast<const float4*>(g_spat)[(size_t)b * 16384 + i];
    float4 o;
    o.x = xv.x * sp.x * s;
    o.y = xv.y * sp.y * s;
    o.z = xv.z * sp.z * s;
    o.w = xv.w * sp.w * s;
    reinterpret_cast<float4*>(out)[(size_t)bc * 16384 + i] = o;
}

// ================= launch (fork-join overlap inside the captured graph) =================
extern "C" void kernel_launch(void* const* d_in, const int* in_sizes, int n_in,
                              void* d_out, int out_size) {
    const float* xe   = (const float*)d_in[0];
    const float* xd   = (const float*)d_in[1];
    const float* cwea = (const float*)d_in[2];
    const float* cbea = (const float*)d_in[3];
    const float* cwem = (const float*)d_in[4];
    const float* cbem = (const float*)d_in[5];
    const float* cwda = (const float*)d_in[6];
    const float* cbda = (const float*)d_in[7];
    const float* cwdm = (const float*)d_in[8];
    const float* cbdm = (const float*)d_in[9];
    const float* cwf  = (const float*)d_in[10];
    const float* cbf  = (const float*)d_in[11];
    const float* sw1e = (const float*)d_in[12];
    const float* sb1e = (const float*)d_in[13];
    const float* sw2e = (const float*)d_in[14];
    const float* sb2e = (const float*)d_in[15];
    const float* sw1d = (const float*)d_in[16];
    const float* sb1d = (const float*)d_in[17];
    const float* sw2d = (const float*)d_in[18];
    const float* sb2d = (const float*)d_in[19];
    float* out = (float*)d_out;

    cudaStream_t s2;
    cudaStreamCreateWithFlags(&s2, cudaStreamNonBlocking);
    cudaEvent_t e1, e2, e3, e4;
    cudaEventCreateWithFlags(&e1, cudaEventDisableTiming);
    cudaEventCreateWithFlags(&e2, cudaEventDisableTiming);
    cudaEventCreateWithFlags(&e3, cudaEventDisableTiming);
    cudaEventCreateWithFlags(&e4, cudaEventDisableTiming);

    k_init<<<1, 1024>>>();

    // fork: dec_pix (issue-bound) concurrent with enc (DRAM-bound)
    cudaEventRecord(e1, 0);
    cudaStreamWaitEvent(s2, e1, 0);
    k_dec_pix<<<dim3(64, 2, 4), 256, 0, s2>>>(xd, sw1d);
    k_enc<<<dim3(128, 4), 128>>>(xe, sw1e, sb1e);
    cudaEventRecord(e2, s2);
    cudaStreamWaitEvent(0, e2, 0);

    // fork: conv concurrent with mlp chain
    cudaEventRecord(e3, 0);
    cudaStreamWaitEvent(s2, e3, 0);
    k_conv<<<dim3(16, 16, 4), 256, 0, s2>>>(sw2e, sw2d, sb2e, sb2d, sb1d);
    k_mlp1<<<dim3(16, 4), 128>>>(cwea, cbea, cwem, cbem, cwda, cbda, cwdm, cbdm);
    k_mlp2<<<1, 512>>>(cwf, cbf);
    cudaEventRecord(e4, s2);
    cudaStreamWaitEvent(0, e4, 0);

    k_final<<<dim3(64, 512), 256>>>(xe, out);

    cudaEventDestroy(e1);
    cudaEventDestroy(e2);
    cudaEventDestroy(e3);
    cudaEventDestroy(e4);
    cudaStreamDestroy(s2);
}

// round 15
// speedup vs baseline: 1.7474x; 1.1080x over previous
#include <cuda_runtime.h>
#include <math.h>

#define HW 65536
#define RATIO (127.0f / 255.0f)

// ---------------- scratch (device globals; no allocation) ----------------
__device__ __align__(16) float g_sage[4 * 3 * HW];  // enc planes: mx, av, c1(+b1)
__device__ __align__(16) float g_sagd[8 * 3 * HW];  // dec PARTIAL planes per (half,b): mx, sum, dot
__device__ __align__(16) float g_spat[4 * HW];      // sigmoid spatial gate
__device__ float    g_encsum[4 * 128];
__device__ unsigned g_encmax[4 * 128];
__device__ float    g_decsum[4 * 256];
__device__ unsigned g_decmax[4 * 256];
__device__ float    g_tsm[64];                      // MLP hidden pre-acts
__device__ __align__(16) float g_ch[4 * 128];       // sigmoid channel gate

// monotone float<->uint map for atomicMax/REDUX-max on floats
__device__ __forceinline__ unsigned f2o(float f) {
    unsigned u = __float_as_uint(f);
    return (u & 0x80000000u) ? ~u : (u | 0x80000000u);
}
__device__ __forceinline__ float o2f(unsigned u) {
    return (u & 0x80000000u) ? __uint_as_float(u & 0x7fffffffu) : __uint_as_float(~u);
}

// ================= init (atomic targets) =================
__global__ void k_init() {
    int t = blockIdx.x * blockDim.x + threadIdx.x;
    if (t < 512)  { g_encsum[t] = 0.f; g_encmax[t] = 0u; }
    if (t < 1024) { g_decsum[t] = 0.f; g_decmax[t] = 0x80000000u; }  // f2o(0); relu => v>=0
}

// ================= fused encoder: planes + channel stats =================
// grid (128, 4) x 128 threads: block = 2 rows; thread = (row, float4-col)
__global__ void __launch_bounds__(128) k_enc(const float* __restrict__ xe,
                                             const float* __restrict__ sw1e,
                                             const float* __restrict__ sb1e) {
    __shared__ float    sw[128];
    __shared__ float    psum[4][128];
    __shared__ unsigned pmax[4][128];
    const int t = threadIdx.x;
    if (t < 128) sw[t] = sw1e[t];
    __syncthreads();
    const int y = blockIdx.x * 2 + (t >> 6), c4 = t & 63, b = blockIdx.y;
    const int warp = t >> 5, lane = t & 31;
    const float4* base = (const float4*)(xe + (size_t)b * 128 * HW + y * 256) + c4;

    float4 mx = make_float4(-3.4e38f, -3.4e38f, -3.4e38f, -3.4e38f);
    float4 sm = make_float4(0.f, 0.f, 0.f, 0.f);
    float4 dt = make_float4(0.f, 0.f, 0.f, 0.f);
    float    racc[4] = {0.f, 0.f, 0.f, 0.f};
    unsigned rmx[4]  = {0u, 0u, 0u, 0u};

#pragma unroll
    for (int q = 0; q < 4; q++) {
#pragma unroll 4
        for (int cc = 0; cc < 32; cc++) {
            const int c = q * 32 + cc;
            float4 v = base[(size_t)c * (HW / 4)];
            float wc = sw[c];
            mx.x = fmaxf(mx.x, v.x); sm.x += v.x; dt.x = fmaf(wc, v.x, dt.x);
            mx.y = fmaxf(mx.y, v.y); sm.y += v.y; dt.y = fmaf(wc, v.y, dt.y);
            mx.z = fmaxf(mx.z, v.z); sm.z += v.z; dt.z = fmaf(wc, v.z, dt.z);
            mx.w = fmaxf(mx.w, v.w); sm.w += v.w; dt.w = fmaf(wc, v.w, dt.w);
            float cs = (v.x + v.y) + (v.z + v.w);
            float cm = fmaxf(fmaxf(v.x, v.y), fmaxf(v.z, v.w));
#pragma unroll
            for (int o = 16; o; o >>= 1)
                cs += __shfl_xor_sync(0xffffffffu, cs, o);
            unsigned rm = __reduce_max_sync(0xffffffffu, f2o(cm));
            if (lane == cc) { racc[q] += cs; rmx[q] = max(rmx[q], rm); }
        }
    }
#pragma unroll
    for (int q = 0; q < 4; q++) {
        psum[warp][q * 32 + lane] = racc[q];
        pmax[warp][q * 32 + lane] = rmx[q];
    }
    __syncthreads();
    if (t < 128) {
        float s = (psum[0][t] + psum[1][t]) + (psum[2][t] + psum[3][t]);
        unsigned m = max(max(pmax[0][t], pmax[1][t]), max(pmax[2][t], pmax[3][t]));
        atomicAdd(&g_encsum[b * 128 + t], s);
        atomicMax(&g_encmax[b * 128 + t], m);
    }
    const float b1 = sb1e[0];
    sm.x *= (1.f / 128.f); sm.y *= (1.f / 128.f); sm.z *= (1.f / 128.f); sm.w *= (1.f / 128.f);
    dt.x += b1; dt.y += b1; dt.z += b1; dt.w += b1;
    const size_t p4 = (size_t)(y * 256) / 4 + c4;
    float4* eb = (float4*)(g_sage + (size_t)b * 3 * HW);
    eb[p4]              = mx;
    eb[HW / 4 + p4]     = sm;
    eb[2 * HW / 4 + p4] = dt;
}

// ================= fused decoder: partial planes + channel stats =================
// grid (64, 2, 4): x = row-group (4 rows), y = channel half, z = b. 256 threads = columns.
__global__ void __launch_bounds__(256) k_dec_pix(const float* __restrict__ xd,
                                                 const float* __restrict__ sw1d) {
    __shared__ float    sw[128];
    __shared__ float    buf[2][8 * 512];   // [buf][q*512 + srcrow*128 + col]
    __shared__ float    psum[8][128];
    __shared__ unsigned pmaxs[8][128];
    const int t = threadIdx.x, half = blockIdx.y, b = blockIdx.z;
    const int warp = t >> 5, lane = t & 31;
    const int y0 = blockIdx.x * 4;
    if (t < 128) sw[t] = sw1d[half * 128 + t];

    const int rbase = (y0 * 127) / 255;
    int lo[4]; float wy[4];
#pragma unroll
    for (int k = 0; k < 4; k++) {
        const int y = y0 + k;
        const int i0 = (y * 127) / 255;          // exact floor
        lo[k] = i0 - rbase;                      // 0..2, uniform per block
        wy[k] = (float)y * RATIO - (float)i0;
    }
    float px = (float)t * RATIO;
    int j0 = min((int)floorf(px), 127), j1 = min(j0 + 1, 127);
    float wx = px - (float)j0;

    const int gA = min(rbase + (t >> 7), 127) * 128 + (t & 127);
    const int gB = min(rbase + 2 + (t >> 7), 127) * 128 + (t & 127);
    const float* pcb = xd + ((size_t)b * 256 + half * 128) * 16384;

#pragma unroll
    for (int q = 0; q < 8; q++) {
        buf[0][q * 512 + t]       = pcb[(size_t)q * 16384 + gA];
        buf[0][q * 512 + 256 + t] = pcb[(size_t)q * 16384 + gB];
    }
    __syncthreads();

    float mx[4] = {0, 0, 0, 0}, sm[4] = {0, 0, 0, 0}, dt[4] = {0, 0, 0, 0};
    float    racc[4] = {0.f, 0.f, 0.f, 0.f};
    unsigned rmx[4]  = {0x80000000u, 0x80000000u, 0x80000000u, 0x80000000u};

#pragma unroll
    for (int s = 0; s < 4; s++) {            // 32-channel slot (compile-time)
        for (int gi = 0; gi < 4; gi++) {     // 8-channel group within slot
            const int g = s * 4 + gi;
            const int cur = g & 1;
            float rr[16];
            const bool pf = (g < 15);
            if (pf) {
                const float* pn = pcb + (size_t)(g + 1) * 8 * 16384;
#pragma unroll
                for (int q = 0; q < 8; q++) {
                    rr[q * 2]     = pn[(size_t)q * 16384 + gA];
                    rr[q * 2 + 1] = pn[(size_t)q * 16384 + gB];
                }
            }
#pragma unroll
            for (int q = 0; q < 8; q++) {
                const int c = g * 8 + q;
                const float* S = &buf[cur][q * 512];
                float h0, h1, h2, h3;
                { float a = S[j0],       bb = S[j1];       h0 = fmaf(wx, bb - a, a); }
                { float a = S[128 + j0], bb = S[128 + j1]; h1 = fmaf(wx, bb - a, a); }
                { float a = S[256 + j0], bb = S[256 + j1]; h2 = fmaf(wx, bb - a, a); }
                { float a = S[384 + j0], bb = S[384 + j1]; h3 = fmaf(wx, bb - a, a); }
                const float wc = sw[c];
                float cs = 0.f, cm = 0.f;
#pragma unroll
                for (int k = 0; k < 4; k++) {
                    float hl = (lo[k] == 0) ? h0 : ((lo[k] == 1) ? h1 : h2);
                    float hh = (lo[k] == 0) ? h1 : ((lo[k] == 1) ? h2 : h3);
                    float v = fmaf(wy[k], hh - hl, hl);
                    v = fmaxf(v, 0.f);
                    mx[k] = fmaxf(mx[k], v);
                    sm[k] += v;
                    dt[k] = fmaf(wc, v, dt[k]);
                    cs += v;
                    cm = fmaxf(cm, v);
                }
#pragma unroll
                for (int o = 16; o; o >>= 1)
                    cs += __shfl_xor_sync(0xffffffffu, cs, o);
                unsigned rm = __reduce_max_sync(0xffffffffu, f2o(cm));
                if (lane == (c & 31)) { racc[s] += cs; rmx[s] = max(rmx[s], rm); }
            }
            if (pf) {
#pragma unroll
                for (int q = 0; q < 8; q++) {
                    buf[cur ^ 1][q * 512 + t]       = rr[q * 2];
                    buf[cur ^ 1][q * 512 + 256 + t] = rr[q * 2 + 1];
                }
            }
            __syncthreads();
        }
    }
    // bank stats: cross-warp combine, one atomic pair per (block, channel)
#pragma unroll
    for (int s = 0; s < 4; s++) {
        psum[warp][s * 32 + lane]  = racc[s];
        pmaxs[warp][s * 32 + lane] = rmx[s];
    }
    __syncthreads();
    if (t < 128) {
        float    ssum = 0.f;
        unsigned smx  = 0x80000000u;
#pragma unroll
        for (int w = 0; w < 8; w++) {
            ssum += psum[w][t];
            smx = max(smx, pmaxs[w][t]);
        }
        atomicAdd(&g_decsum[b * 256 + half * 128 + t], ssum);
        atomicMax(&g_decmax[b * 256 + half * 128 + t], smx);
    }
    const size_t db = (size_t)(half * 4 + b) * 3 * HW;
#pragma unroll
    for (int k = 0; k < 4; k++) {
        const int p = (y0 + k) * 256 + t;
        g_sagd[db + p]          = mx[k];
        g_sagd[db + HW + p]     = sm[k];
        g_sagd[db + 2 * HW + p] = dt[k];
    }
}

// ================= channel MLP stage 1: hidden pre-activations =================
// grid (16, 4): n = blockIdx.x, b = blockIdx.y; 128 threads
__global__ void __launch_bounds__(128) k_mlp1(
        const float* __restrict__ cwea, const float* __restrict__ cbea,
        const float* __restrict__ cwem, const float* __restrict__ cbem,
        const float* __restrict__ cwda, const float* __restrict__ cbda,
        const float* __restrict__ cwdm, const float* __restrict__ cbdm) {
    __shared__ float red[128];
    const int n = blockIdx.x, b = blockIdx.y, t = threadIdx.x;
    float acc = g_encsum[b * 128 + t] * (1.f / 65536.f) * cwea[n * 128 + t]
              + o2f(g_encmax[b * 128 + t]) * cwem[n * 128 + t];
    acc += g_decsum[b * 256 + t] * (1.f / 65536.f) * cwda[n * 256 + t]
         + o2f(g_decmax[b * 256 + t]) * cwdm[n * 256 + t];
    acc += g_decsum[b * 256 + 128 + t] * (1.f / 65536.f) * cwda[n * 256 + 128 + t]
         + o2f(g_decmax[b * 256 + 128 + t]) * cwdm[n * 256 + 128 + t];
    if (t == 0) acc += cbea[n] + cbem[n] + cbda[n] + cbdm[n];
    red[t] = acc;
    __syncthreads();
    for (int o = 64; o > 0; o >>= 1) {
        if (t < o) red[t] += red[t + o];
        __syncthreads();
    }
    if (t == 0) g_tsm[b * 16 + n] = red[0];
}

// ================= channel MLP stage 2: 16 -> 128 sigmoid =================
__global__ void __launch_bounds__(512) k_mlp2(const float* __restrict__ cwf,
                                              const float* __restrict__ cbf) {
    const int t = threadIdx.x;              // 512: b = t>>7, o = t&127
    const int b = t >> 7, o = t & 127;
    float a = cbf[o];
#pragma unroll
    for (int q = 0; q < 16; q++) a = fmaf(g_tsm[b * 16 + q], cwf[o * 16 + q], a);
    g_ch[t] = 1.f / (1.f + __expf(-a));
}

// ================= fused 7x7 conv: strip-mined, weights in registers =================
// grid (8, 8, 4): 32x32 output tile, 256 threads, 4 vertical outputs/thread.
__global__ void __launch_bounds__(256) k_conv(const float* __restrict__ sw2e,
                                              const float* __restrict__ sw2d,
                                              const float* __restrict__ sb2e,
                                              const float* __restrict__ sb2d,
                                              const float* __restrict__ sb1d) {
    __shared__ float pl[6][38 * 38];
    __shared__ float wsm[294];
    __shared__ float bv;
    const int tid = threadIdx.x;
    const int X0 = blockIdx.x * 32, Y0 = blockIdx.y * 32, b = blockIdx.z;
    for (int i = tid; i < 294; i += 256)
        wsm[i] = (i < 147) ? sw2e[i] : sw2d[i - 147];
    if (tid == 0) bv = sb2e[0] + sb2d[0];
    const float sb1 = __ldg(sb1d);
    const size_t eb = (size_t)b * 3 * HW;
    const size_t d0 = (size_t)b * 3 * HW;        // half 0
    const size_t d1 = (size_t)(4 + b) * 3 * HW;  // half 1
    for (int idx = tid; idx < 38 * 38; idx += 256) {
        int ry = idx / 38, rx = idx - ry * 38;
        int gy = Y0 + ry - 3, gx = X0 + rx - 3;
        float v0 = 0, v1 = 0, v2 = 0, v3 = 0, v4 = 0, v5 = 0;
        if (gy >= 0 && gy < 256 && gx >= 0 && gx < 256) {
            int p = gy * 256 + gx;
            v0 = g_sage[eb + p];
            v1 = g_sage[eb + HW + p];
            v2 = g_sage[eb + 2 * HW + p];
            v3 = fmaxf(g_sagd[d0 + p], g_sagd[d1 + p]);
            v4 = (g_sagd[d0 + HW + p] + g_sagd[d1 + HW + p]) * (1.f / 256.f);
            v5 = g_sagd[d0 + 2 * HW + p] + g_sagd[d1 + 2 * HW + p] + sb1;
        }
        pl[0][idx] = v0; pl[1][idx] = v1; pl[2][idx] = v2;
        pl[3][idx] = v3; pl[4][idx] = v4; pl[5][idx] = v5;
    }
    __syncthreads();

    const int tx = tid & 31, ty = tid >> 5;      // thread = column tx, rows 4*ty..4*ty+3
    float acc[4];
#pragma unroll
    for (int k = 0; k < 4; k++) acc[k] = bv;

    for (int p = 0; p < 6; p++) {
        float w[49];
#pragma unroll
        for (int k = 0; k < 49; k++) w[k] = wsm[p * 49 + k];
#pragma unroll
        for (int iy = 0; iy < 10; iy++) {
            const float* rp = &pl[p][(ty * 4 + iy) * 38 + tx];
            float s0 = rp[0], s1 = rp[1], s2 = rp[2], s3 = rp[3], s4 = rp[4], s5 = rp[5], s6 = rp[6];
#pragma unroll
            for (int ro = 0; ro < 4; ro++) {
                const int dy = iy - ro;
                if (dy >= 0 && dy < 7) {
                    float a = acc[ro];
                    a = fmaf(s0, w[dy * 7 + 0], a);
                    a = fmaf(s1, w[dy * 7 + 1], a);
                    a = fmaf(s2, w[dy * 7 + 2], a);
                    a = fmaf(s3, w[dy * 7 + 3], a);
                    a = fmaf(s4, w[dy * 7 + 4], a);
                    a = fmaf(s5, w[dy * 7 + 5], a);
                    a = fmaf(s6, w[dy * 7 + 6], a);
                    acc[ro] = a;
                }
            }
        }
    }
#pragma unroll
    for (int ro = 0; ro < 4; ro++) {
        float sg = 1.f / (1.f + __expf(-acc[ro]));
        g_spat[(size_t)b * HW + (Y0 + ty * 4 + ro) * 256 + X0 + tx] = sg;
    }
}

// ================= final multiply =================
__global__ void __launch_bounds__(256) k_final(const float* __restrict__ xe,
                                               float* __restrict__ out) {
    const int bc = blockIdx.y;
    const int b  = bc >> 7;
    const int i  = blockIdx.x * 256 + threadIdx.x;
    const float s = g_ch[bc];
    float4 xv = reinterpret_cast<const float4*>(xe)[(size_t)bc * 16384 + i];
    float4 sp = reinterpret_cast<const float4*>(g_spat)[(size_t)b * 16384 + i];
    float4 o;
    o.x = xv.x * sp.x * s;
    o.y = xv.y * sp.y * s;
    o.z = xv.z * sp.z * s;
    o.w = xv.w * sp.w * s;
    reinterpret_cast<float4*>(out)[(size_t)bc * 16384 + i] = o;
}

// ================= launch (fork-join overlap inside the captured graph) =================
extern "C" void kernel_launch(void* const* d_in, const int* in_sizes, int n_in,
                              void* d_out, int out_size) {
    const float* xe   = (const float*)d_in[0];
    const float* xd   = (const float*)d_in[1];
    const float* cwea = (const float*)d_in[2];
    const float* cbea = (const float*)d_in[3];
    const float* cwem = (const float*)d_in[4];
    const float* cbem = (const float*)d_in[5];
    const float* cwda = (const float*)d_in[6];
    const float* cbda = (const float*)d_in[7];
    const float* cwdm = (const float*)d_in[8];
    const float* cbdm = (const float*)d_in[9];
    const float* cwf  = (const float*)d_in[10];
    const float* cbf  = (const float*)d_in[11];
    const float* sw1e = (const float*)d_in[12];
    const float* sb1e = (const float*)d_in[13];
    const float* sw2e = (const float*)d_in[14];
    const float* sb2e = (const float*)d_in[15];
    const float* sw1d = (const float*)d_in[16];
    const float* sb1d = (const float*)d_in[17];
    const float* sw2d = (const float*)d_in[18];
    const float* sb2d = (const float*)d_in[19];
    float* out = (float*)d_out;

    cudaStream_t s2;
    cudaStreamCreateWithFlags(&s2, cudaStreamNonBlocking);
    cudaEvent_t e1, e2, e3, e4;
    cudaEventCreateWithFlags(&e1, cudaEventDisableTiming);
    cudaEventCreateWithFlags(&e2, cudaEventDisableTiming);
    cudaEventCreateWithFlags(&e3, cudaEventDisableTiming);
    cudaEventCreateWithFlags(&e4, cudaEventDisableTiming);

    k_init<<<1, 1024>>>();

    // fork: dec_pix (issue-bound) concurrent with enc (DRAM-bound)
    cudaEventRecord(e1, 0);
    cudaStreamWaitEvent(s2, e1, 0);
    k_dec_pix<<<dim3(64, 2, 4), 256, 0, s2>>>(xd, sw1d);
    k_enc<<<dim3(128, 4), 128>>>(xe, sw1e, sb1e);
    cudaEventRecord(e2, s2);
    cudaStreamWaitEvent(0, e2, 0);

    // fork: conv concurrent with mlp chain
    cudaEventRecord(e3, 0);
    cudaStreamWaitEvent(s2, e3, 0);
    k_conv<<<dim3(8, 8, 4), 256, 0, s2>>>(sw2e, sw2d, sb2e, sb2d, sb1d);
    k_mlp1<<<dim3(16, 4), 128>>>(cwea, cbea, cwem, cbem, cwda, cbda, cwdm, cbdm);
    k_mlp2<<<1, 512>>>(cwf, cbf);
    cudaEventRecord(e4, s2);
    cudaStreamWaitEvent(0, e4, 0);

    k_final<<<dim3(64, 512), 256>>>(xe, out);

    cudaEventDestroy(e1);
    cudaEventDestroy(e2);
    cudaEventDestroy(e3);
    cudaEventDestroy(e4);
    cudaStreamDestroy(s2);
}